// round 6
// baseline (speedup 1.0000x reference)
#include <cuda_runtime.h>
#include <cstdint>
#include <math.h>

#define BATCH   8192
#define D_IN    2048
#define D_HID   16384
#define KSEL    64
#define KAUX    512

// ---------------- scratch (static device globals; no dynamic allocation) -------------
__device__ float    g_pre[(size_t)BATCH * D_HID];      // 512 MB pre-activations
__device__ float    g_WT[(size_t)D_HID * D_IN];        // 128 MB W_dec transposed [16384,2048]
__device__ int      g_sel_idx[BATCH * KSEL];
__device__ float    g_sel_val[BATCH * KSEL];
__device__ int      g_aux_idx[(size_t)BATCH * KAUX];
__device__ float    g_aux_val[(size_t)BATCH * KAUX];
__device__ float    g_recon_p[BATCH];
__device__ float    g_aux_p[BATCH];
__device__ float    g_l0_p[BATCH];
__device__ unsigned g_deadbits[D_HID / 32];

// ---------------- helpers ----------------
__device__ __forceinline__ uint32_t f2key(float f) {
    uint32_t u = __float_as_uint(f);
    return (u & 0x80000000u) ? ~u : (u | 0x80000000u);
}
__device__ __forceinline__ float key2f(uint32_t k) {
    uint32_t u = (k & 0x80000000u) ? (k ^ 0x80000000u) : ~k;
    return __uint_as_float(u);
}

// ---------------- dead_mask prep: detect bool(u8) vs int32 serialization, pack bitset --
__global__ void prep_mask(const uint8_t* __restrict__ m) {
    __shared__ int viol;
    if (threadIdx.x == 0) viol = 0;
    __syncthreads();
    for (int i = threadIdx.x; i < D_HID; i += blockDim.x)
        if ((i & 3) && m[i]) viol = 1;
    __syncthreads();
    const bool is_i32 = (viol == 0);
    const int* mi = (const int*)m;
    for (int w = threadIdx.x; w < D_HID / 32; w += blockDim.x) {
        uint32_t bits = 0;
        #pragma unroll 4
        for (int b = 0; b < 32; ++b) {
            int j = w * 32 + b;
            bool d = is_i32 ? (mi[j] != 0) : (m[j] != 0);
            bits |= ((uint32_t)d) << b;
        }
        g_deadbits[w] = bits;
    }
}

// ---------------- W_dec transpose: [2048,16384] -> [16384,2048] ----------------
__global__ void transpose_wdec(const float* __restrict__ W) {
    __shared__ float t[32][33];
    int x = blockIdx.x * 32 + threadIdx.x;   // hidden idx
    int y0 = blockIdx.y * 32;                // input idx base
    #pragma unroll
    for (int i = threadIdx.y; i < 32; i += 8)
        t[i][threadIdx.x] = W[(size_t)(y0 + i) * D_HID + x];
    __syncthreads();
    int xo = y0 + threadIdx.x;
    int yo0 = blockIdx.x * 32;
    #pragma unroll
    for (int i = threadIdx.y; i < 32; i += 8)
        g_WT[(size_t)(yo0 + i) * D_IN + xo] = t[threadIdx.x][i];
}

// ---------------- encoder GEMM: pre = (x - b_dec) @ W_enc^T + b_enc ----------------
// Emulates Eigen gebp panel-blocked accumulation (XLA:CPU reference path):
//   kc = 248 (aarch64 NEON: mr=12, nr=4, default l1=16KB, kr=8)
//   per output: master = sum over ascending panels of (serial ascending FMA chain
//   over the 248 k-values of that panel); master += panel is a plain fp32 add.
// Tile 128(M) x 64(N), BK=16, 256 threads, 8x4 microtile (master+panel regs).
__global__ __launch_bounds__(256, 2) void encoder_gemm(
    const float* __restrict__ X, const float* __restrict__ WE,
    const float* __restrict__ be, const float* __restrict__ bd)
{
    __shared__ float As[16 * 132];
    __shared__ float Bs[16 * 68];
    const int tid = threadIdx.x;
    const int tx = tid & 15, ty = tid >> 4;          // tx: n (4 each), ty: m (8 each)
    const int m0 = blockIdx.y * 128, n0 = blockIdx.x * 64;

    // A-load mapping: 128 rows x 16 k = 512 float4 -> 2 float4/thread
    const int arow = tid >> 1;            // 0..127
    const int ac8  = (tid & 1) * 8;       // k sub-offset 0 or 8
    // B-load mapping: 64 rows x 16 k = 256 float4 -> 1 float4/thread
    const int brow = tid >> 2;            // 0..63
    const int bc4  = (tid & 3) * 4;       // k sub-offset 0,4,8,12

    const float* Ap = X + (size_t)(m0 + arow) * D_IN + ac8;
    const float* Bp = WE + (size_t)(n0 + brow) * D_IN + bc4;

    float acc[8][4], pan[8][4];
    #pragma unroll
    for (int i = 0; i < 8; ++i)
        #pragma unroll
        for (int j = 0; j < 4; ++j) { acc[i][j] = 0.f; pan[i][j] = 0.f; }

    for (int k0 = 0; k0 < D_IN; k0 += 16) {
        float4 a0 = *(const float4*)(Ap + k0);
        float4 a1 = *(const float4*)(Ap + k0 + 4);
        float4 b0 = *(const float4*)(Bp + k0);
        float4 d0 = *(const float4*)(bd + k0 + ac8);
        float4 d1 = *(const float4*)(bd + k0 + ac8 + 4);
        a0.x -= d0.x; a0.y -= d0.y; a0.z -= d0.z; a0.w -= d0.w;
        a1.x -= d1.x; a1.y -= d1.y; a1.z -= d1.z; a1.w -= d1.w;
        __syncthreads();
        As[(ac8 + 0) * 132 + arow] = a0.x;
        As[(ac8 + 1) * 132 + arow] = a0.y;
        As[(ac8 + 2) * 132 + arow] = a0.z;
        As[(ac8 + 3) * 132 + arow] = a0.w;
        As[(ac8 + 4) * 132 + arow] = a1.x;
        As[(ac8 + 5) * 132 + arow] = a1.y;
        As[(ac8 + 6) * 132 + arow] = a1.z;
        As[(ac8 + 7) * 132 + arow] = a1.w;
        Bs[(bc4 + 0) * 68 + brow] = b0.x;
        Bs[(bc4 + 1) * 68 + brow] = b0.y;
        Bs[(bc4 + 2) * 68 + brow] = b0.z;
        Bs[(bc4 + 3) * 68 + brow] = b0.w;
        __syncthreads();

        const bool foldMid = ((k0 % 496) == 240);                 // boundary at k0+8
        const bool foldEnd = (((k0 + 16) % 496) == 0) || (k0 + 16 == D_IN);

        #pragma unroll
        for (int kk = 0; kk < 8; ++kk) {
            float a[8], b[4];
            *(float4*)(a)     = *(const float4*)&As[kk * 132 + ty * 8];
            *(float4*)(a + 4) = *(const float4*)&As[kk * 132 + ty * 8 + 4];
            *(float4*)(b)     = *(const float4*)&Bs[kk * 68 + tx * 4];
            #pragma unroll
            for (int i = 0; i < 8; ++i)
                #pragma unroll
                for (int j = 0; j < 4; ++j)
                    pan[i][j] += a[i] * b[j];
        }
        if (foldMid) {
            #pragma unroll
            for (int i = 0; i < 8; ++i)
                #pragma unroll
                for (int j = 0; j < 4; ++j) { acc[i][j] += pan[i][j]; pan[i][j] = 0.f; }
        }
        #pragma unroll
        for (int kk = 8; kk < 16; ++kk) {
            float a[8], b[4];
            *(float4*)(a)     = *(const float4*)&As[kk * 132 + ty * 8];
            *(float4*)(a + 4) = *(const float4*)&As[kk * 132 + ty * 8 + 4];
            *(float4*)(b)     = *(const float4*)&Bs[kk * 68 + tx * 4];
            #pragma unroll
            for (int i = 0; i < 8; ++i)
                #pragma unroll
                for (int j = 0; j < 4; ++j)
                    pan[i][j] += a[i] * b[j];
        }
        if (foldEnd) {
            #pragma unroll
            for (int i = 0; i < 8; ++i)
                #pragma unroll
                for (int j = 0; j < 4; ++j) { acc[i][j] += pan[i][j]; pan[i][j] = 0.f; }
        }
    }

    float4 bev = *(const float4*)(be + n0 + tx * 4);
    #pragma unroll
    for (int i = 0; i < 8; ++i) {
        size_t row = (size_t)(m0 + ty * 8 + i) * D_HID + n0 + tx * 4;
        float4 o = make_float4(acc[i][0] + bev.x, acc[i][1] + bev.y,
                               acc[i][2] + bev.z, acc[i][3] + bev.w);
        *(float4*)&g_pre[row] = o;
    }
}

// ---------------- exact radix-select (top-K threshold on monotone uint keys) --------
__device__ void radix_select(const uint32_t* keys, const uint32_t* deadb, bool useMask,
                             uint32_t* hist, int K, uint32_t* outT, int* outNeed, int lane)
{
    uint32_t prefix = 0;
    int kk = K;
    #pragma unroll 1
    for (int level = 0; level < 4; ++level) {
        const int shift = 24 - 8 * level;
        for (int b = threadIdx.x; b < 256; b += blockDim.x) hist[b] = 0;
        __syncthreads();
        const uint32_t hmask = (level == 0) ? 0u : (0xFFFFFFFFu << (shift + 8));
        for (int j = threadIdx.x; j < D_HID; j += blockDim.x) {
            uint32_t k = keys[j];
            if (useMask && !((deadb[j >> 5] >> (j & 31)) & 1u)) k = 0u;
            const bool valid = ((k & hmask) == prefix);
            const int bin = (int)((k >> shift) & 255u);
            const int tag = valid ? bin : (256 + lane);
            const unsigned grp = __match_any_sync(0xFFFFFFFFu, tag);
            if (valid && lane == (__ffs(grp) - 1))
                atomicAdd(&hist[bin], (uint32_t)__popc(grp));
        }
        __syncthreads();
        if (threadIdx.x == 0) {
            int acc = 0, b = 255;
            for (; b > 0; --b) {
                int c = (int)hist[b];
                if (acc + c >= kk) break;
                acc += c;
            }
            hist[256] = (uint32_t)b;
            hist[257] = (uint32_t)(kk - acc);
        }
        __syncthreads();
        prefix |= (hist[256] << shift);
        kk = (int)hist[257];
        __syncthreads();
    }
    *outT = prefix;
    *outNeed = kk;
}

// ---------------- per-row topk: z scatter + (idx,val) lists for both selections -----
__global__ __launch_bounds__(256) void topk_kernel(float* __restrict__ z_out)
{
    extern __shared__ uint32_t sm[];
    uint32_t* keys  = sm;              // 16384
    uint32_t* deadb = sm + 16384;      // 512
    uint32_t* hist  = sm + 16896;      // 258 (+pad)
    int*      eq    = (int*)(sm + 17160); // 64
    int*      ctr   = (int*)(sm + 17224); // [0]=cnt [1]=eqcnt [2]=l0

    const int tid = threadIdx.x;
    const int lane = tid & 31;
    const int r = blockIdx.x;
    const size_t base = (size_t)r * D_HID;

    for (int j = tid; j < D_HID; j += 256) keys[j] = f2key(g_pre[base + j]);
    for (int w = tid; w < D_HID / 32; w += 256) deadb[w] = g_deadbits[w];
    __syncthreads();

    // ===== main top-64 =====
    uint32_t T; int needEq;
    radix_select(keys, deadb, false, hist, KSEL, &T, &needEq, lane);

    if (tid == 0) { ctr[0] = 0; ctr[1] = 0; ctr[2] = 0; }
    __syncthreads();
    for (int j = tid; j < D_HID; j += 256)
        if (keys[j] == T) { int p = atomicAdd(&ctr[1], 1); if (p < 64) eq[p] = j; }
    __syncthreads();
    if (tid == 0) {
        int m = min(ctr[1], 64);
        int take = min(needEq, m);
        for (int a = 0; a < take; ++a) {           // lowest-index ties first
            int best = a;
            for (int b = a + 1; b < m; ++b) if (eq[b] < eq[best]) best = b;
            int t2 = eq[a]; eq[a] = eq[best]; eq[best] = t2;
        }
        ctr[1] = take;
    }
    __syncthreads();
    const int nEq = ctr[1];
    for (int j = tid; j < D_HID; j += 256) {
        uint32_t k = keys[j];
        bool sel = (k > T);
        if (!sel && k == T)
            for (int a = 0; a < nEq; ++a) if (eq[a] == j) { sel = true; break; }
        float v = key2f(k);
        z_out[base + j] = sel ? fmaxf(v, 0.f) : 0.f;
        if (sel) {
            int p = atomicAdd(&ctr[0], 1);
            if (p < KSEL) { g_sel_idx[r * KSEL + p] = j; g_sel_val[r * KSEL + p] = v; }
            if (v > 0.f) atomicAdd(&ctr[2], 1);
        }
    }
    __syncthreads();
    if (tid == 0) {
        g_l0_p[r] = (float)ctr[2];
        for (int p = min(ctr[0], KSEL); p < KSEL; ++p) {   // safety pad
            g_sel_idx[r * KSEL + p] = 0; g_sel_val[r * KSEL + p] = -1.f;
        }
    }
    __syncthreads();

    // ===== aux top-512 among dead features =====
    uint32_t Ta; int needEqA;
    radix_select(keys, deadb, true, hist, KAUX, &Ta, &needEqA, lane);
    if (tid == 0) { ctr[0] = 0; ctr[1] = 0; }
    __syncthreads();
    for (int j = tid; j < D_HID; j += 256) {
        uint32_t k = ((deadb[j >> 5] >> (j & 31)) & 1u) ? keys[j] : 0u;
        if (k != 0u && k == Ta) { int p = atomicAdd(&ctr[1], 1); if (p < 64) eq[p] = j; }
    }
    __syncthreads();
    if (tid == 0) {
        int m = min(ctr[1], 64);
        int take = min(needEqA, m);
        for (int a = 0; a < take; ++a) {
            int best = a;
            for (int b = a + 1; b < m; ++b) if (eq[b] < eq[best]) best = b;
            int t2 = eq[a]; eq[a] = eq[best]; eq[best] = t2;
        }
        ctr[1] = take;
    }
    __syncthreads();
    const int nEqA = ctr[1];
    for (int j = tid; j < D_HID; j += 256) {
        uint32_t k = ((deadb[j >> 5] >> (j & 31)) & 1u) ? keys[j] : 0u;
        bool sel = (k > Ta);
        if (!sel && k != 0u && k == Ta)
            for (int a = 0; a < nEqA; ++a) if (eq[a] == j) { sel = true; break; }
        if (sel) {
            int p = atomicAdd(&ctr[0], 1);
            if (p < KAUX) { g_aux_idx[(size_t)r * KAUX + p] = j; g_aux_val[(size_t)r * KAUX + p] = key2f(keys[j]); }
        }
    }
    __syncthreads();
    if (tid == 0)
        for (int p = min(ctr[0], KAUX); p < KAUX; ++p) {
            g_aux_idx[(size_t)r * KAUX + p] = 0; g_aux_val[(size_t)r * KAUX + p] = -1.f;
        }
}

// ---------------- sparse decode: x_hat = z @ W_dec^T + b_dec, recon partials --------
__global__ __launch_bounds__(256) void decode_main(const float* __restrict__ X,
                                                   float* __restrict__ xhat,
                                                   const float* __restrict__ bd)
{
    __shared__ int s_idx[KSEL];
    __shared__ float s_val[KSEL];
    __shared__ float red[8];
    const int tid = threadIdx.x, r = blockIdx.x;
    if (tid < KSEL) {
        s_idx[tid] = g_sel_idx[r * KSEL + tid];
        s_val[tid] = fmaxf(g_sel_val[r * KSEL + tid], 0.f);
    }
    __syncthreads();
    const float4* bd4 = (const float4*)bd;
    float4 acc0 = bd4[tid], acc1 = bd4[tid + 256];
    #pragma unroll 4
    for (int s = 0; s < KSEL; ++s) {
        float v = s_val[s];
        const float4* w = (const float4*)(g_WT + (size_t)s_idx[s] * D_IN);
        float4 w0 = w[tid], w1 = w[tid + 256];
        acc0.x += v * w0.x; acc0.y += v * w0.y; acc0.z += v * w0.z; acc0.w += v * w0.w;
        acc1.x += v * w1.x; acc1.y += v * w1.y; acc1.z += v * w1.z; acc1.w += v * w1.w;
    }
    const size_t b4 = (size_t)r * (D_IN / 4);
    ((float4*)xhat)[b4 + tid] = acc0;
    ((float4*)xhat)[b4 + tid + 256] = acc1;
    const float4* X4 = (const float4*)X;
    float4 x0 = X4[b4 + tid], x1 = X4[b4 + tid + 256];
    float d, loc = 0.f;
    d = acc0.x - x0.x; loc += d * d;  d = acc0.y - x0.y; loc += d * d;
    d = acc0.z - x0.z; loc += d * d;  d = acc0.w - x0.w; loc += d * d;
    d = acc1.x - x1.x; loc += d * d;  d = acc1.y - x1.y; loc += d * d;
    d = acc1.z - x1.z; loc += d * d;  d = acc1.w - x1.w; loc += d * d;
    #pragma unroll
    for (int o = 16; o; o >>= 1) loc += __shfl_down_sync(0xFFFFFFFFu, loc, o);
    if ((tid & 31) == 0) red[tid >> 5] = loc;
    __syncthreads();
    if (tid == 0) {
        float s = 0.f;
        for (int w2 = 0; w2 < 8; ++w2) s += red[w2];
        g_recon_p[r] = s;
    }
}

// ---------------- aux decode: e_hat row + aux partials ----------------
__global__ __launch_bounds__(256) void decode_aux(const float* __restrict__ X,
                                                  const float* __restrict__ xhat)
{
    __shared__ int s_idx[KAUX];
    __shared__ float s_val[KAUX];
    __shared__ float red[8];
    const int tid = threadIdx.x, r = blockIdx.x;
    for (int s = tid; s < KAUX; s += 256) {
        s_idx[s] = g_aux_idx[(size_t)r * KAUX + s];
        s_val[s] = fmaxf(g_aux_val[(size_t)r * KAUX + s], 0.f);
    }
    __syncthreads();
    float4 acc0 = make_float4(0.f, 0.f, 0.f, 0.f);
    float4 acc1 = make_float4(0.f, 0.f, 0.f, 0.f);
    #pragma unroll 4
    for (int s = 0; s < KAUX; ++s) {
        float v = s_val[s];
        const float4* w = (const float4*)(g_WT + (size_t)s_idx[s] * D_IN);
        float4 w0 = w[tid], w1 = w[tid + 256];
        acc0.x += v * w0.x; acc0.y += v * w0.y; acc0.z += v * w0.z; acc0.w += v * w0.w;
        acc1.x += v * w1.x; acc1.y += v * w1.y; acc1.z += v * w1.z; acc1.w += v * w1.w;
    }
    const size_t b4 = (size_t)r * (D_IN / 4);
    const float4* X4 = (const float4*)X;
    const float4* H4 = (const float4*)xhat;
    float4 x0 = X4[b4 + tid], x1 = X4[b4 + tid + 256];
    float4 h0 = H4[b4 + tid], h1 = H4[b4 + tid + 256];
    float d, loc = 0.f;
    d = acc0.x - (x0.x - h0.x); loc += d * d;  d = acc0.y - (x0.y - h0.y); loc += d * d;
    d = acc0.z - (x0.z - h0.z); loc += d * d;  d = acc0.w - (x0.w - h0.w); loc += d * d;
    d = acc1.x - (x1.x - h1.x); loc += d * d;  d = acc1.y - (x1.y - h1.y); loc += d * d;
    d = acc1.z - (x1.z - h1.z); loc += d * d;  d = acc1.w - (x1.w - h1.w); loc += d * d;
    #pragma unroll
    for (int o = 16; o; o >>= 1) loc += __shfl_down_sync(0xFFFFFFFFu, loc, o);
    if ((tid & 31) == 0) red[tid >> 5] = loc;
    __syncthreads();
    if (tid == 0) {
        float s = 0.f;
        for (int w2 = 0; w2 < 8; ++w2) s += red[w2];
        g_aux_p[r] = s;
    }
}

// ---------------- final scalar reduction (double accumulation) ----------------
__global__ void finalize_kernel(float* __restrict__ outs)
{
    __shared__ double sd[256];
    const int tid = threadIdx.x;
    double s = 0.0;
    for (int i = tid; i < BATCH; i += 256) s += (double)g_recon_p[i];
    sd[tid] = s; __syncthreads();
    for (int o = 128; o > 0; o >>= 1) { if (tid < o) sd[tid] += sd[tid + o]; __syncthreads(); }
    double recon = sd[0] / ((double)BATCH * (double)D_IN);
    __syncthreads();

    s = 0.0;
    for (int i = tid; i < BATCH; i += 256) s += (double)g_aux_p[i];
    sd[tid] = s; __syncthreads();
    for (int o = 128; o > 0; o >>= 1) { if (tid < o) sd[tid] += sd[tid + o]; __syncthreads(); }
    double aux = sd[0] / ((double)BATCH * (double)D_IN);
    __syncthreads();

    s = 0.0;
    for (int i = tid; i < BATCH; i += 256) s += (double)g_l0_p[i];
    sd[tid] = s; __syncthreads();
    for (int o = 128; o > 0; o >>= 1) { if (tid < o) sd[tid] += sd[tid + o]; __syncthreads(); }
    double l0 = sd[0] / (double)BATCH;

    if (tid == 0) {
        outs[0] = (float)(recon + aux * (1.0 / 32.0));  // loss
        outs[1] = (float)recon;
        outs[2] = (float)aux;
        outs[3] = (float)l0;
    }
}

// ---------------- launch ----------------
extern "C" void kernel_launch(void* const* d_in, const int* in_sizes, int n_in,
                              void* d_out, int out_size) {
    (void)in_sizes; (void)n_in; (void)out_size;
    const float* X  = (const float*)d_in[0];
    const float* WE = (const float*)d_in[1];
    const float* be = (const float*)d_in[2];
    const float* WD = (const float*)d_in[3];
    const float* bd = (const float*)d_in[4];
    const uint8_t* dm = (const uint8_t*)d_in[5];

    float* out = (float*)d_out;
    float* xhat = out;                                    // [8192, 2048]
    float* z = out + (size_t)BATCH * D_IN;                // [8192, 16384]
    float* scalars = z + (size_t)BATCH * D_HID;           // loss, recon, aux, l0

    cudaFuncSetAttribute(topk_kernel, cudaFuncAttributeMaxDynamicSharedMemorySize, 70 * 1024);

    prep_mask<<<1, 512>>>(dm);
    transpose_wdec<<<dim3(D_HID / 32, D_IN / 32), dim3(32, 8)>>>(WD);
    encoder_gemm<<<dim3(D_HID / 64, BATCH / 128), 256>>>(X, WE, be, bd);
    topk_kernel<<<BATCH, 256, 70 * 1024>>>(z);
    decode_main<<<BATCH, 256>>>(X, xhat, bd);
    decode_aux<<<BATCH, 256>>>(X, xhat);
    finalize_kernel<<<1, 256>>>(scalars);
}